// round 1
// baseline (speedup 1.0000x reference)
#include <cuda_runtime.h>
#include <math.h>

#define NA    24564          // anchors per batch
#define NAP   24576          // padded: 1024 segments * 24
#define NB    32             // batch
#define NCH   93
#define TOPK  200
#define NEGV  (-1e10f)
#define CONF_TH 0.01f
#define IOU_TH  0.45f

// scratch (device globals: no allocation allowed)
__device__ float  g_scores[NB * NAP];
__device__ float4 g_boxes [NB * NAP];
__device__ float  g_cls   [NB * NAP];

// ---------------------------------------------------------------------------
// Kernel 1: decode. One warp per anchor. Reads 93 contiguous floats,
// computes class argmax/max (channels 0..80), decodes box (channels 81..92).
// ---------------------------------------------------------------------------
__global__ void decode_kernel(const float* __restrict__ y)
{
    const int warp_in_blk = threadIdx.x >> 5;
    const int lane        = threadIdx.x & 31;
    const int anchor      = blockIdx.x * (blockDim.x >> 5) + warp_in_blk;
    const int b           = blockIdx.y;
    if (anchor >= NA) return;

    const float* p = y + ((size_t)b * NA + anchor) * NCH;

    const float v0 = p[lane];
    const float v1 = p[lane + 32];
    const float v2 = (lane < 29) ? p[lane + 64] : NEGV;

    // local class argmax (indices: lane, lane+32, lane+64 if < 81)
    float best = v0; int bidx = lane;
    if (v1 > best)                { best = v1; bidx = lane + 32; }
    if (lane < 17 && v2 > best)   { best = v2; bidx = lane + 64; }

    // warp reduce: max value, ties -> lowest index (matches jnp.argmax)
    #pragma unroll
    for (int off = 16; off; off >>= 1) {
        float ov = __shfl_xor_sync(0xffffffffu, best, off);
        int   oi = __shfl_xor_sync(0xffffffffu, bidx, off);
        if (ov > best || (ov == best && oi < bidx)) { best = ov; bidx = oi; }
    }

    // broadcast tail channels 81..92 (held by lanes 17..28 of v2)
    const float y81 = __shfl_sync(0xffffffffu, v2, 17);
    const float y82 = __shfl_sync(0xffffffffu, v2, 18);
    const float y83 = __shfl_sync(0xffffffffu, v2, 19);
    const float y84 = __shfl_sync(0xffffffffu, v2, 20);
    const float y85 = __shfl_sync(0xffffffffu, v2, 21);
    const float y86 = __shfl_sync(0xffffffffu, v2, 22);
    const float y87 = __shfl_sync(0xffffffffu, v2, 23);
    const float y88 = __shfl_sync(0xffffffffu, v2, 24);
    const float y89 = __shfl_sync(0xffffffffu, v2, 25);
    const float y90 = __shfl_sync(0xffffffffu, v2, 26);
    const float y91 = __shfl_sync(0xffffffffu, v2, 27);
    const float y92 = __shfl_sync(0xffffffffu, v2, 28);

    if (lane == 0) {
        const float cx = y81 * y89 * y87 + y85;
        const float cy = y82 * y90 * y88 + y86;
        const float w  = expf(y83 * y91) * y87;
        const float h  = expf(y84 * y92) * y88;

        float4 box;
        box.x = (cx - 0.5f * w) * 512.0f;   // xmin
        box.y = (cy - 0.5f * h) * 512.0f;   // ymin
        box.z = (cx + 0.5f * w) * 512.0f;   // xmax
        box.w = (cy + 0.5f * h) * 512.0f;   // ymax

        const bool valid = (bidx != 0) && (best > CONF_TH);
        const int  idx   = b * NAP + anchor;
        g_scores[idx] = valid ? best : NEGV;
        g_boxes [idx] = box;
        g_cls   [idx] = (float)bidx;
    }
}

// ---------------------------------------------------------------------------
// Kernel 2: NMS. One CTA per batch. Scores live in SMEM under a 3-level max
// tree (24576 -> 1024 -> 32). A single warp pops global argmax repeatedly,
// lazily rejecting candidates that overlap (IoU > 0.45) any accepted box.
// First 200 accepted rows (descending conf) == reference output.
// ---------------------------------------------------------------------------
__device__ __forceinline__ float warp_max_f(float v)
{
    #pragma unroll
    for (int o = 16; o; o >>= 1)
        v = fmaxf(v, __shfl_xor_sync(0xffffffffu, v, o));
    return v;
}

__device__ __forceinline__ void warp_argmax(float& v, int& i)
{
    #pragma unroll
    for (int o = 16; o; o >>= 1) {
        float ov = __shfl_xor_sync(0xffffffffu, v, o);
        int   oi = __shfl_xor_sync(0xffffffffu, i, o);
        if (ov > v || (ov == v && oi < i)) { v = ov; i = oi; }
    }
}

__global__ void __launch_bounds__(1024, 1) nms_kernel(float* __restrict__ out)
{
    extern __shared__ float sm[];
    float*  s        = sm;                       // NAP scores
    float*  segmax   = sm + NAP;                 // 1024
    float*  supermax = segmax + 1024;            // 32
    float4* abox     = (float4*)(supermax + 32); // 200 accepted boxes

    const int b   = blockIdx.x;
    const int tid = threadIdx.x;

    // zero the output slab for this batch
    for (int j = tid; j < TOPK * 6; j += 1024)
        out[b * TOPK * 6 + j] = 0.0f;

    // load scores to SMEM (pad with NEG)
    const float* gs = g_scores + b * NAP;
    for (int j = tid; j < NAP; j += 1024)
        s[j] = (j < NA) ? gs[j] : NEGV;
    __syncthreads();

    // level-1 maxima: thread t owns s[t*24 .. t*24+23]
    {
        float m = NEGV;
        const int base = tid * 24;
        #pragma unroll
        for (int k = 0; k < 24; k++) m = fmaxf(m, s[base + k]);
        segmax[tid] = m;
    }
    __syncthreads();

    // level-2 maxima
    if (tid < 32) {
        float m = NEGV;
        #pragma unroll
        for (int k = 0; k < 32; k++) m = fmaxf(m, segmax[tid * 32 + k]);
        supermax[tid] = m;
    }
    __syncthreads();

    if (tid >= 32) return;   // warp 0 runs the pop loop alone (no barriers)

    const int     lane = tid;
    const float4* gb   = g_boxes + b * NAP;
    const float*  gc   = g_cls   + b * NAP;

    int acc = 0;
    while (acc < TOPK) {
        // ---- level 2: pick group ----
        float v = supermax[lane]; int g = lane;
        warp_argmax(v, g);
        if (v <= NEGV * 0.5f) break;            // nothing valid left

        // ---- level 1: pick segment within group ----
        float v1 = segmax[g * 32 + lane]; int l1 = lane;
        warp_argmax(v1, l1);
        const int seg = g * 32 + l1;

        // ---- level 0: pick element within segment ----
        float v0 = (lane < 24) ? s[seg * 24 + lane] : NEGV;
        int   k  = (lane < 24) ? lane : 1000;
        warp_argmax(v0, k);
        const int   i    = seg * 24 + k;
        const float conf = v;                    // the popped (max) score

        // remove popped element; rebuild level-1/level-2 maxima incrementally
        {
            float held = (lane < 24) ? s[seg * 24 + lane] : NEGV;
            if (lane == k) held = NEGV;
            const float nsm = warp_max_f(held);
            if (lane == 0) { s[i] = NEGV; segmax[seg] = nsm; }
        }
        __syncwarp();
        {
            const float sv  = segmax[g * 32 + lane];
            const float nsu = warp_max_f(sv);
            if (lane == 0) supermax[g] = nsu;
        }

        // fetch candidate box (broadcast from lane 0)
        float4 box;
        if (lane == 0) box = __ldg(&gb[i]);
        box.x = __shfl_sync(0xffffffffu, box.x, 0);
        box.y = __shfl_sync(0xffffffffu, box.y, 0);
        box.z = __shfl_sync(0xffffffffu, box.z, 0);
        box.w = __shfl_sync(0xffffffffu, box.w, 0);

        // lazy suppression: IoU against accepted set (rounding-exact, no FMA)
        bool sup = false;
        for (int a = lane; a < acc; a += 32) {
            const float4 ab = abox[a];
            const float ix1 = fmaxf(box.x, ab.x);
            const float iy1 = fmaxf(box.y, ab.y);
            const float ix2 = fminf(box.z, ab.z);
            const float iy2 = fminf(box.w, ab.w);
            const float iw  = fmaxf(__fsub_rn(ix2, ix1), 0.0f);
            const float ih  = fmaxf(__fsub_rn(iy2, iy1), 0.0f);
            const float inter = __fmul_rn(iw, ih);
            const float a1  = __fmul_rn(__fsub_rn(box.z, box.x), __fsub_rn(box.w, box.y));
            const float a2  = __fmul_rn(__fsub_rn(ab.z,  ab.x),  __fsub_rn(ab.w,  ab.y));
            const float uni = __fsub_rn(__fadd_rn(a1, a2), inter);
            if (uni > 0.0f && __fdiv_rn(inter, uni) > IOU_TH) sup = true;
        }
        sup = (__ballot_sync(0xffffffffu, sup) != 0u);

        if (!sup) {
            if (lane == 0) {
                abox[acc] = box;
                float* o = out + ((size_t)b * TOPK + acc) * 6;
                o[0] = __ldg(&gc[i]);
                o[1] = conf;
                o[2] = box.x; o[3] = box.y; o[4] = box.z; o[5] = box.w;
            }
            acc++;
        }
        __syncwarp();
    }
}

// ---------------------------------------------------------------------------
extern "C" void kernel_launch(void* const* d_in, const int* in_sizes, int n_in,
                              void* d_out, int out_size)
{
    const float* y   = (const float*)d_in[0];
    float*       out = (float*)d_out;

    // decode: one warp per anchor, 8 warps per block
    dim3 dgrid((NA + 7) / 8, NB);
    decode_kernel<<<dgrid, 256>>>(y);

    // NMS: one CTA per batch, 105728 B dynamic SMEM (opt-in each call; API is
    // not a stream op, so it is graph-capture safe and deterministic)
    const int smem_bytes = (NAP + 1024 + 32) * 4 + TOPK * 16;
    cudaFuncSetAttribute(nms_kernel, cudaFuncAttributeMaxDynamicSharedMemorySize,
                         smem_bytes);
    nms_kernel<<<NB, 1024, smem_bytes>>>(out);
}

// round 2
// speedup vs baseline: 1.1562x; 1.1562x over previous
#include <cuda_runtime.h>
#include <math.h>

#define NA    24564          // anchors per batch
#define NAP   24576          // padded: 48 chunks * 512
#define NB    32             // batch
#define NCH   93
#define TOPK  200
#define NEGV  (-1e10f)
#define CONF_TH 0.01f
#define IOU_TH  0.45f
#define NCHUNK 48
#define CHSZ   512

typedef unsigned long long u64;
typedef unsigned int u32;

// scratch (device globals: no allocation allowed)
__device__ u64    g_keys [NB * NAP];   // mono(conf)<<32 | (~anchor); 0 if invalid
__device__ float4 g_boxes[NB * NAP];
__device__ float  g_cls  [NB * NAP];

// ---------------------------------------------------------------------------
// Kernel 1: decode. Block = 256 threads handles 256 anchors of one batch.
// Cooperative float4 load of the 256*93 contiguous floats into SMEM,
// then one thread per anchor: serial argmax over 81 classes + box decode.
// ---------------------------------------------------------------------------
__global__ void __launch_bounds__(256) decode_kernel(const float* __restrict__ y)
{
    extern __shared__ float s[];          // up to 256*93 floats (95232 B)
    const int b   = blockIdx.y;
    const int a0  = blockIdx.x * 256;
    const int cnt = min(256, NA - a0);
    const int tid = threadIdx.x;

    const float* base = y + ((size_t)b * NA + a0) * NCH;
    const int nvec = (cnt * NCH) >> 2;    // cnt is always multiple of 4
    const float4* b4 = (const float4*)base;
    float4* s4 = (float4*)s;
    for (int i = tid; i < nvec; i += 256) s4[i] = b4[i];
    __syncthreads();

    if (tid >= cnt) return;
    const float* r = s + tid * NCH;

    float best = r[0]; int bi = 0;
    #pragma unroll
    for (int c = 1; c < 81; c++) {
        const float v = r[c];
        if (v > best) { best = v; bi = c; }   // first-max => lowest index
    }

    const float y81 = r[81], y82 = r[82], y83 = r[83], y84 = r[84];
    const float y85 = r[85], y86 = r[86], y87 = r[87], y88 = r[88];
    const float y89 = r[89], y90 = r[90], y91 = r[91], y92 = r[92];

    const float cx = y81 * y89 * y87 + y85;
    const float cy = y82 * y90 * y88 + y86;
    const float w  = expf(y83 * y91) * y87;
    const float h  = expf(y84 * y92) * y88;

    float4 box;
    box.x = (cx - 0.5f * w) * 512.0f;
    box.y = (cy - 0.5f * h) * 512.0f;
    box.z = (cx + 0.5f * w) * 512.0f;
    box.w = (cy + 0.5f * h) * 512.0f;

    const int  anchor = a0 + tid;
    const int  idx    = b * NAP + anchor;
    const bool valid  = (bi != 0) && (best > CONF_TH);
    // best > 0.01 > 0  =>  monotone key = bits | signbit
    const u32 mono = __float_as_uint(best) | 0x80000000u;
    g_keys [idx] = valid ? (((u64)mono << 32) | (u64)(0xFFFFFFFFu - (u32)anchor))
                         : 0ull;
    g_boxes[idx] = box;
    g_cls  [idx] = (float)bi;
}

// ---------------------------------------------------------------------------
// Kernel 2: NMS. One CTA (1024 thr) per batch.
//  - 32 warps load + bitonic-sort 48 chunks of 512 u64 keys (descending).
//  - warp 0 walks candidates in global descending order via a 48-way
//    tournament over chunk heads (head box/class pre-fetched per lane),
//    lazily rejecting IoU>0.45 vs accepted set in SMEM. Stops at 200.
// ---------------------------------------------------------------------------
__global__ void __launch_bounds__(1024, 1) nms_kernel(float* __restrict__ out)
{
    extern __shared__ u64 sk[];                 // NAP keys
    float4* abox = (float4*)(sk + NAP);         // 200 accepted boxes

    const int b    = blockIdx.x;
    const int tid  = threadIdx.x;
    const int lane = tid & 31;
    const int wid  = tid >> 5;

    // zero output slab
    for (int j = tid; j < TOPK * 6; j += 1024)
        out[b * TOPK * 6 + j] = 0.0f;

    const u64* gk = g_keys + (size_t)b * NAP;

    // per-warp: load + sort chunks (no block barriers inside)
    for (int c = wid; c < NCHUNK; c += 32) {
        const int base = c * CHSZ;
        for (int t = lane; t < CHSZ; t += 32) {
            const int j = base + t;
            sk[j] = (j < NA) ? gk[j] : 0ull;
        }
        __syncwarp();
        // bitonic sort, descending
        for (int k = 2; k <= CHSZ; k <<= 1) {
            for (int j = k >> 1; j; j >>= 1) {
                for (int v = lane; v < CHSZ / 2; v += 32) {
                    const int t = ((v & ~(j - 1)) << 1) | (v & (j - 1));
                    const int p = t | j;
                    const u64 A = sk[base + t];
                    const u64 B = sk[base + p];
                    const bool desc = ((t & k) == 0);
                    if (desc ? (A < B) : (A > B)) {
                        sk[base + t] = B;
                        sk[base + p] = A;
                    }
                }
                __syncwarp();
            }
        }
    }
    __syncthreads();
    if (tid >= 32) return;     // warp 0 only from here

    const float4* gb = g_boxes + (size_t)b * NAP;
    const float*  gc = g_cls   + (size_t)b * NAP;

    // per-lane chunk heads: lane owns chunk `lane`, lanes<16 also `lane+32`
    int p0 = lane * CHSZ, e0 = p0 + CHSZ;
    u64 k0 = sk[p0];
    float4 b0 = make_float4(0.f, 0.f, 0.f, 0.f); float c0v = 0.f;
    if (k0) { const int a_ = (int)(0xFFFFFFFFu - (u32)k0); b0 = __ldg(&gb[a_]); c0v = __ldg(&gc[a_]); }

    int p1 = 0, e1 = 0;
    u64 k1 = 0;
    float4 b1 = make_float4(0.f, 0.f, 0.f, 0.f); float c1v = 0.f;
    if (lane < NCHUNK - 32) {
        p1 = (lane + 32) * CHSZ; e1 = p1 + CHSZ;
        k1 = sk[p1];
        if (k1) { const int a_ = (int)(0xFFFFFFFFu - (u32)k1); b1 = __ldg(&gb[a_]); c1v = __ldg(&gc[a_]); }
    }

    int acc = 0;
    while (acc < TOPK) {
        const bool use0 = (k0 >= k1);
        const u64  mk   = use0 ? k0 : k1;

        // warp-wide u64 max via two u32 redux
        const u32 hi = (u32)(mk >> 32);
        const u32 mh = __reduce_max_sync(0xffffffffu, hi);
        const u32 lo = (hi == mh) ? (u32)mk : 0u;
        const u32 ml = __reduce_max_sync(0xffffffffu, lo);
        const u64 wkey = ((u64)mh << 32) | ml;
        if (wkey == 0ull) break;                    // exhausted

        const bool iwin = (mk == wkey);             // unique winner
        const u32  wb   = __ballot_sync(0xffffffffu, iwin);
        const int  wl   = __ffs(wb) - 1;

        // broadcast winner's cached box + class (registers, no L2 on pop path)
        const float4 src  = use0 ? b0 : b1;
        const float  scls = use0 ? c0v : c1v;
        float4 wbx;
        wbx.x = __shfl_sync(0xffffffffu, src.x, wl);
        wbx.y = __shfl_sync(0xffffffffu, src.y, wl);
        wbx.z = __shfl_sync(0xffffffffu, src.z, wl);
        wbx.w = __shfl_sync(0xffffffffu, src.w, wl);
        const float wcls = __shfl_sync(0xffffffffu, scls, wl);

        // lazy suppression vs accepted set (rounding-exact, no FMA)
        bool sup = false;
        for (int a = lane; a < acc; a += 32) {
            const float4 ab = abox[a];
            const float ix1 = fmaxf(wbx.x, ab.x);
            const float iy1 = fmaxf(wbx.y, ab.y);
            const float ix2 = fminf(wbx.z, ab.z);
            const float iy2 = fminf(wbx.w, ab.w);
            const float iw  = fmaxf(__fsub_rn(ix2, ix1), 0.0f);
            const float ih  = fmaxf(__fsub_rn(iy2, iy1), 0.0f);
            const float inter = __fmul_rn(iw, ih);
            const float a1  = __fmul_rn(__fsub_rn(wbx.z, wbx.x), __fsub_rn(wbx.w, wbx.y));
            const float a2  = __fmul_rn(__fsub_rn(ab.z,  ab.x),  __fsub_rn(ab.w,  ab.y));
            const float uni = __fsub_rn(__fadd_rn(a1, a2), inter);
            if (uni > 0.0f && __fdiv_rn(inter, uni) > IOU_TH) sup = true;
        }
        sup = (__ballot_sync(0xffffffffu, sup) != 0u);

        if (!sup) {
            if (lane == 0) {
                abox[acc] = wbx;
                float* o = out + ((size_t)b * TOPK + acc) * 6;
                o[0] = wcls;
                o[1] = __uint_as_float(mh ^ 0x80000000u);   // conf
                o[2] = wbx.x; o[3] = wbx.y; o[4] = wbx.z; o[5] = wbx.w;
            }
            acc++;
        }

        // advance winner's chunk head; prefetch its new box/class
        if (iwin) {
            if (use0) {
                p0++;
                k0 = (p0 < e0) ? sk[p0] : 0ull;
                if (k0) { const int a_ = (int)(0xFFFFFFFFu - (u32)k0); b0 = __ldg(&gb[a_]); c0v = __ldg(&gc[a_]); }
            } else {
                p1++;
                k1 = (p1 < e1) ? sk[p1] : 0ull;
                if (k1) { const int a_ = (int)(0xFFFFFFFFu - (u32)k1); b1 = __ldg(&gb[a_]); c1v = __ldg(&gc[a_]); }
            }
        }
        __syncwarp();
    }
}

// ---------------------------------------------------------------------------
extern "C" void kernel_launch(void* const* d_in, const int* in_sizes, int n_in,
                              void* d_out, int out_size)
{
    const float* y   = (const float*)d_in[0];
    float*       out = (float*)d_out;

    // decode: block of 256 threads per 256 anchors
    const int dec_smem = 256 * NCH * 4;   // 95232 B
    cudaFuncSetAttribute(decode_kernel,
                         cudaFuncAttributeMaxDynamicSharedMemorySize, dec_smem);
    dim3 dgrid((NA + 255) / 256, NB);
    decode_kernel<<<dgrid, 256, dec_smem>>>(y);

    // NMS: one CTA per batch
    const int nms_smem = NAP * 8 + TOPK * 16;   // 199808 B
    cudaFuncSetAttribute(nms_kernel,
                         cudaFuncAttributeMaxDynamicSharedMemorySize, nms_smem);
    nms_kernel<<<NB, 1024, nms_smem>>>(out);
}

// round 4
// speedup vs baseline: 1.4173x; 1.2258x over previous
#include <cuda_runtime.h>
#include <math.h>

#define NA     24564          // anchors per batch
#define NAP    24576          // padded: 12 chunks * 2048
#define NB     32             // batch
#define NCH    93
#define TOPK   200
#define CONF_TH 0.01f
#define IOU_TH  0.45f
#define NCHUNK 12
#define CHSZ   2048

typedef unsigned long long u64;
typedef unsigned int u32;

// scratch (device globals: no allocation allowed)
__device__ u64    g_keys [NB * NAP];   // mono(conf)<<32 | (~anchor); 0 if invalid
__device__ float4 g_boxes[NB * NAP];
__device__ float  g_cls  [NB * NAP];

// ---------------------------------------------------------------------------
// Kernel 1: decode. Block = 256 threads handles 128 anchors of one batch.
// float4-coalesced load into SMEM, then one thread per anchor.
// 47.6 KB SMEM -> 4 CTAs/SM resident.
// ---------------------------------------------------------------------------
__global__ void __launch_bounds__(256) decode_kernel(const float* __restrict__ y)
{
    extern __shared__ float smF[];        // 128*93 floats (47616 B)
    const int b   = blockIdx.y;
    const int a0  = blockIdx.x * 128;
    const int cnt = min(128, NA - a0);
    const int tid = threadIdx.x;

    const float* base = y + ((size_t)b * NA + a0) * NCH;
    const int nvec = (cnt * NCH) >> 2;    // cnt always multiple of 4
    const float4* b4 = (const float4*)base;
    float4* s4 = (float4*)smF;
    #pragma unroll 4
    for (int i = tid; i < nvec; i += 256) s4[i] = b4[i];
    __syncthreads();

    if (tid >= cnt) return;
    const float* r = smF + tid * NCH;     // stride 93 (odd) -> conflict-free

    float best = r[0]; int bi = 0;
    #pragma unroll
    for (int c = 1; c < 81; c++) {
        const float v = r[c];
        if (v > best) { best = v; bi = c; }   // first-max => lowest index
    }

    const float y81 = r[81], y82 = r[82], y83 = r[83], y84 = r[84];
    const float y85 = r[85], y86 = r[86], y87 = r[87], y88 = r[88];
    const float y89 = r[89], y90 = r[90], y91 = r[91], y92 = r[92];

    const float cx = y81 * y89 * y87 + y85;
    const float cy = y82 * y90 * y88 + y86;
    const float w  = expf(y83 * y91) * y87;
    const float h  = expf(y84 * y92) * y88;

    float4 box;
    box.x = (cx - 0.5f * w) * 512.0f;
    box.y = (cy - 0.5f * h) * 512.0f;
    box.z = (cx + 0.5f * w) * 512.0f;
    box.w = (cy + 0.5f * h) * 512.0f;

    const int  anchor = a0 + tid;
    const int  idx    = b * NAP + anchor;
    const bool valid  = (bi != 0) && (best > CONF_TH);
    const u32  mono   = __float_as_uint(best) | 0x80000000u;  // best>0
    g_keys [idx] = valid ? (((u64)mono << 32) | (u64)(0xFFFFFFFFu - (u32)anchor))
                         : 0ull;
    g_boxes[idx] = box;
    g_cls  [idx] = (float)bi;
}

// ---------------------------------------------------------------------------
// Kernel 2: chunk sort. Grid (NCHUNK, NB), 1024 threads. Each CTA bitonic-
// sorts one 2048-key chunk (descending) in SMEM, in place in g_keys.
// One compare-swap per thread per stage; 66 stages.
// ---------------------------------------------------------------------------
__global__ void __launch_bounds__(1024) sort_kernel()
{
    extern __shared__ u64 smS[];          // 2048 keys (16 KB)
    const int b    = blockIdx.y;
    const int base = blockIdx.x * CHSZ;   // within batch
    const int tid  = threadIdx.x;
    u64* gk = g_keys + (size_t)b * NAP + base;

    {
        const int j0 = tid, j1 = tid + 1024;
        smS[j0] = (base + j0 < NA) ? gk[j0] : 0ull;
        smS[j1] = (base + j1 < NA) ? gk[j1] : 0ull;
    }

    for (int k = 2; k <= CHSZ; k <<= 1) {
        for (int j = k >> 1; j; j >>= 1) {
            __syncthreads();
            const int t = ((tid & ~(j - 1)) << 1) | (tid & (j - 1));
            const int p = t | j;
            const u64 A = smS[t];
            const u64 B = smS[p];
            const bool desc = ((t & k) == 0);
            if (desc ? (A < B) : (A > B)) { smS[t] = B; smS[p] = A; }
        }
    }
    __syncthreads();
    gk[tid]        = smS[tid];
    gk[tid + 1024] = smS[tid + 1024];
}

// ---------------------------------------------------------------------------
// Kernel 3: walk. One CTA (1024 thr) per batch: copy sorted keys into SMEM,
// then warp 0 pops candidates in global descending order via a 12-way
// tournament (heads on lanes 0..11, box/class prefetched into registers),
// lazily rejecting IoU>0.45 vs accepted set. Stops at 200 accepts.
// ---------------------------------------------------------------------------
__global__ void __launch_bounds__(1024, 1) nms_kernel(float* __restrict__ out)
{
    extern __shared__ u64 sk[];                 // NAP keys
    float4* abox = (float4*)(sk + NAP);         // 200 accepted boxes

    const int b    = blockIdx.x;
    const int tid  = threadIdx.x;
    const int lane = tid & 31;

    // zero output slab
    for (int j = tid; j < TOPK * 6; j += 1024)
        out[b * TOPK * 6 + j] = 0.0f;

    // copy keys (sorted per chunk) into SMEM
    const u64* gk = g_keys + (size_t)b * NAP;
    #pragma unroll 4
    for (int j = tid; j < NAP; j += 1024) sk[j] = gk[j];
    __syncthreads();
    if (tid >= 32) return;                      // warp 0 only

    const float4* gb = g_boxes + (size_t)b * NAP;
    const float*  gc = g_cls   + (size_t)b * NAP;

    // heads: lane < 12 owns chunk `lane`
    int p0 = 0, e0 = 0;
    u64 k0 = 0;
    float4 b0 = make_float4(0.f, 0.f, 0.f, 0.f);
    float  c0 = 0.f;
    if (lane < NCHUNK) {
        p0 = lane * CHSZ; e0 = p0 + CHSZ;
        k0 = sk[p0];
        if (k0) { const int a_ = (int)(0xFFFFFFFFu - (u32)k0);
                  b0 = __ldg(&gb[a_]); c0 = __ldg(&gc[a_]); }
    }

    int acc = 0;
    while (acc < TOPK) {
        // warp-wide u64 max via two u32 redux (winner unique: low bits = ~anchor)
        const u32 hi = (u32)(k0 >> 32);
        const u32 mh = __reduce_max_sync(0xffffffffu, hi);
        const u32 lo = (hi == mh) ? (u32)k0 : 0u;
        const u32 ml = __reduce_max_sync(0xffffffffu, lo);
        if (mh == 0u) break;                    // exhausted

        const bool iwin = (hi == mh) && ((u32)k0 == ml);
        const u32  wb   = __ballot_sync(0xffffffffu, iwin);
        const int  wl   = __ffs(wb) - 1;

        // broadcast winner's cached box + class
        float4 wbx;
        wbx.x = __shfl_sync(0xffffffffu, b0.x, wl);
        wbx.y = __shfl_sync(0xffffffffu, b0.y, wl);
        wbx.z = __shfl_sync(0xffffffffu, b0.z, wl);
        wbx.w = __shfl_sync(0xffffffffu, b0.w, wl);
        const float wcls = __shfl_sync(0xffffffffu, c0, wl);

        // lazy suppression vs accepted set (rounding-exact, no FMA)
        bool sup = false;
        for (int a = lane; a < acc; a += 32) {
            const float4 ab = abox[a];
            const float ix1 = fmaxf(wbx.x, ab.x);
            const float iy1 = fmaxf(wbx.y, ab.y);
            const float ix2 = fminf(wbx.z, ab.z);
            const float iy2 = fminf(wbx.w, ab.w);
            const float iw  = fmaxf(__fsub_rn(ix2, ix1), 0.0f);
            const float ih  = fmaxf(__fsub_rn(iy2, iy1), 0.0f);
            const float inter = __fmul_rn(iw, ih);
            const float a1  = __fmul_rn(__fsub_rn(wbx.z, wbx.x), __fsub_rn(wbx.w, wbx.y));
            const float a2  = __fmul_rn(__fsub_rn(ab.z,  ab.x),  __fsub_rn(ab.w,  ab.y));
            const float uni = __fsub_rn(__fadd_rn(a1, a2), inter);
            if (uni > 0.0f && __fdiv_rn(inter, uni) > IOU_TH) sup = true;
        }
        sup = (__ballot_sync(0xffffffffu, sup) != 0u);

        if (!sup) {
            if (lane == wl) {
                abox[acc] = wbx;
                float* o = out + ((size_t)b * TOPK + acc) * 6;
                o[0] = wcls;
                o[1] = __uint_as_float(mh ^ 0x80000000u);   // conf
                o[2] = wbx.x; o[3] = wbx.y; o[4] = wbx.z; o[5] = wbx.w;
            }
            acc++;
        }

        // advance winner's head; prefetch its new box/class
        if (iwin) {
            p0++;
            k0 = (p0 < e0) ? sk[p0] : 0ull;
            if (k0) { const int a_ = (int)(0xFFFFFFFFu - (u32)k0);
                      b0 = __ldg(&gb[a_]); c0 = __ldg(&gc[a_]); }
        }
        __syncwarp();
    }
}

// ---------------------------------------------------------------------------
extern "C" void kernel_launch(void* const* d_in, const int* in_sizes, int n_in,
                              void* d_out, int out_size)
{
    const float* y   = (const float*)d_in[0];
    float*       out = (float*)d_out;

    // decode: 128 anchors per 256-thread CTA
    const int dec_smem = 128 * NCH * 4;   // 47616 B
    cudaFuncSetAttribute(decode_kernel,
                         cudaFuncAttributeMaxDynamicSharedMemorySize, dec_smem);
    dim3 dgrid((NA + 127) / 128, NB);
    decode_kernel<<<dgrid, 256, dec_smem>>>(y);

    // chunk sort: 384 CTAs
    const int sort_smem = CHSZ * 8;       // 16384 B
    cudaFuncSetAttribute(sort_kernel,
                         cudaFuncAttributeMaxDynamicSharedMemorySize, sort_smem);
    dim3 sgrid(NCHUNK, NB);
    sort_kernel<<<sgrid, 1024, sort_smem>>>();

    // walk: one CTA per batch
    const int nms_smem = NAP * 8 + TOPK * 16;   // 199808 B
    cudaFuncSetAttribute(nms_kernel,
                         cudaFuncAttributeMaxDynamicSharedMemorySize, nms_smem);
    nms_kernel<<<NB, 1024, nms_smem>>>(out);
}

// round 5
// speedup vs baseline: 1.7906x; 1.2634x over previous
#include <cuda_runtime.h>
#include <math.h>

#define NA     24564          // anchors per batch
#define NAP    24576          // padded: 12 chunks * 2048
#define NB     32             // batch
#define NCH    93
#define TOPK   200
#define CONF_TH 0.01f
#define IOU_TH  0.45f
#define NCHUNK 12
#define CHSZ   2048
#define SSEL   512            // merged head size (per-chunk top-512)

typedef unsigned long long u64;
typedef unsigned int u32;

// scratch (device globals: no allocation allowed)
__device__ u64    g_keys [NB * NAP];   // mono(conf)<<32 | (~anchor); 0 if invalid
__device__ float4 g_boxes[NB * NAP];
__device__ float  g_cls  [NB * NAP];

// ---------------------------------------------------------------------------
// Kernel 1: decode. 256 threads / 64 anchors -> 23.8KB SMEM, 8 CTAs/SM.
// ---------------------------------------------------------------------------
__global__ void __launch_bounds__(256) decode_kernel(const float* __restrict__ y)
{
    extern __shared__ float smF[];        // 64*93 floats
    const int b   = blockIdx.y;
    const int a0  = blockIdx.x * 64;
    const int cnt = min(64, NA - a0);
    const int tid = threadIdx.x;

    const float* base = y + ((size_t)b * NA + a0) * NCH;
    const int nvec = (cnt * NCH) >> 2;    // cnt multiple of 4
    const float4* b4 = (const float4*)base;
    float4* s4 = (float4*)smF;
    #pragma unroll 2
    for (int i = tid; i < nvec; i += 256) s4[i] = b4[i];
    __syncthreads();

    if (tid >= cnt) return;
    const float* r = smF + tid * NCH;     // stride 93 (odd) -> conflict-free

    float best = r[0]; int bi = 0;
    #pragma unroll
    for (int c = 1; c < 81; c++) {
        const float v = r[c];
        if (v > best) { best = v; bi = c; }   // first-max => lowest index
    }

    const float y81 = r[81], y82 = r[82], y83 = r[83], y84 = r[84];
    const float y85 = r[85], y86 = r[86], y87 = r[87], y88 = r[88];
    const float y89 = r[89], y90 = r[90], y91 = r[91], y92 = r[92];

    const float cx = y81 * y89 * y87 + y85;
    const float cy = y82 * y90 * y88 + y86;
    const float w  = expf(y83 * y91) * y87;
    const float h  = expf(y84 * y92) * y88;

    float4 box;
    box.x = (cx - 0.5f * w) * 512.0f;
    box.y = (cy - 0.5f * h) * 512.0f;
    box.z = (cx + 0.5f * w) * 512.0f;
    box.w = (cy + 0.5f * h) * 512.0f;

    const int  anchor = a0 + tid;
    const int  idx    = b * NAP + anchor;
    const bool valid  = (bi != 0) && (best > CONF_TH);
    const u32  mono   = __float_as_uint(best) | 0x80000000u;  // best>0
    g_keys [idx] = valid ? (((u64)mono << 32) | (u64)(0xFFFFFFFFu - (u32)anchor))
                         : 0ull;
    g_boxes[idx] = box;
    g_cls  [idx] = (float)bi;
}

// ---------------------------------------------------------------------------
// Kernel 2: chunk sort (unchanged). Grid (NCHUNK, NB), 1024 threads; bitonic
// sorts one 2048-key chunk descending, in place in g_keys.
// ---------------------------------------------------------------------------
__global__ void __launch_bounds__(1024) sort_kernel()
{
    extern __shared__ u64 smS[];          // 2048 keys (16 KB)
    const int b    = blockIdx.y;
    const int base = blockIdx.x * CHSZ;
    const int tid  = threadIdx.x;
    u64* gk = g_keys + (size_t)b * NAP + base;

    {
        const int j0 = tid, j1 = tid + 1024;
        smS[j0] = (base + j0 < NA) ? gk[j0] : 0ull;
        smS[j1] = (base + j1 < NA) ? gk[j1] : 0ull;
    }

    for (int k = 2; k <= CHSZ; k <<= 1) {
        for (int j = k >> 1; j; j >>= 1) {
            __syncthreads();
            const int t = ((tid & ~(j - 1)) << 1) | (tid & (j - 1));
            const int p = t | j;
            const u64 A = smS[t];
            const u64 B = smS[p];
            const bool desc = ((t & k) == 0);
            if (desc ? (A < B) : (A > B)) { smS[t] = B; smS[p] = A; }
        }
    }
    __syncthreads();
    gk[tid]        = smS[tid];
    gk[tid + 1024] = smS[tid + 1024];
}

// ---------------------------------------------------------------------------
// Kernel 3: merge-select + walk. One CTA (1024 thr) per batch.
// Prologue: load per-chunk top-SSEL keys, compute each element's exact global
// rank via binary searches, scatter ranks < SSEL into a sorted array gs[].
// Warp 0 then walks gs[] sequentially (prefetched boxes, no tournament).
// Fallback to global tournament if >SSEL candidates are needed (exactness).
// ---------------------------------------------------------------------------
__global__ void __launch_bounds__(1024, 1) nms_kernel(float* __restrict__ out)
{
    extern __shared__ u64 smW[];
    u64*    sh       = smW;                         // NCHUNK * SSEL keys (48KB)
    u64*    gs       = smW + NCHUNK * SSEL;         // SSEL merged keys
    float4* abox     = (float4*)(gs + SSEL);        // TOPK accepted boxes
    int*    chunkcnt = (int*)(abox + TOPK);         // NCHUNK counts

    const int b    = blockIdx.x;
    const int tid  = threadIdx.x;
    const int lane = tid & 31;

    // zero output slab
    for (int j = tid; j < TOPK * 6; j += 1024)
        out[b * TOPK * 6 + j] = 0.0f;

    const u64* gk = g_keys + (size_t)b * NAP;

    // load per-chunk heads
    #pragma unroll
    for (int j = tid; j < NCHUNK * SSEL; j += 1024) {
        const int c = j >> 9;          // / SSEL
        const int i = j & (SSEL - 1);
        sh[j] = gk[c * CHSZ + i];
    }
    if (tid < SSEL) gs[tid] = 0ull;
    if (tid < NCHUNK) chunkcnt[tid] = 0;
    __syncthreads();

    // rank-based merge of heads: 6 elements per thread
    #pragma unroll
    for (int j = tid; j < NCHUNK * SSEL; j += 1024) {
        const int c = j >> 9;
        const int i = j & (SSEL - 1);
        const u64 k = sh[j];
        if (!k) continue;              // zeros never rank < SSEL meaningfully
        int rank = i;
        #pragma unroll
        for (int c2 = 0; c2 < NCHUNK; c2++) {
            if (c2 == c) continue;
            const u64* a = sh + c2 * SSEL;
            int cnt = 0;               // # elements > k (keys unique if nonzero)
            #pragma unroll
            for (int step = SSEL; step > 0; step >>= 1) {
                const int np = cnt + step;
                if (np <= SSEL && a[np - 1] > k) cnt = np;
            }
            rank += cnt;
            if (rank >= SSEL) break;
        }
        if (rank < SSEL) {
            gs[rank] = k;
            atomicAdd(&chunkcnt[c], 1);
        }
    }
    __syncthreads();
    if (tid >= 32) return;             // warp 0 only from here

    const float4* gb = g_boxes + (size_t)b * NAP;
    const float*  gc = g_cls   + (size_t)b * NAP;

    int  acc = 0;
    bool exhausted = false;

    // ---- main walk over merged top-SSEL, 32-candidate supersteps ----
    for (int pos = 0; pos < SSEL && acc < TOPK && !exhausted; pos += 32) {
        const u64 k = gs[pos + lane];
        const u32 vmask = __ballot_sync(0xffffffffu, k != 0ull);

        // prefetch own candidate's box/class
        float4 bx = make_float4(0.f, 0.f, 0.f, 0.f);
        float  cl = 0.f;
        if (k) {
            const int a_ = (int)(0xFFFFFFFFu - (u32)k);
            bx = __ldg(&gb[a_]);
            cl = __ldg(&gc[a_]);
        }

        for (int t = 0; t < 32 && acc < TOPK; t++) {
            if (!((vmask >> t) & 1u)) { exhausted = true; break; }

            float4 wbx;
            wbx.x = __shfl_sync(0xffffffffu, bx.x, t);
            wbx.y = __shfl_sync(0xffffffffu, bx.y, t);
            wbx.z = __shfl_sync(0xffffffffu, bx.z, t);
            wbx.w = __shfl_sync(0xffffffffu, bx.w, t);

            bool sup = false;
            for (int a = lane; a < acc; a += 32) {
                const float4 ab = abox[a];
                const float ix1 = fmaxf(wbx.x, ab.x);
                const float iy1 = fmaxf(wbx.y, ab.y);
                const float ix2 = fminf(wbx.z, ab.z);
                const float iy2 = fminf(wbx.w, ab.w);
                const float iw  = fmaxf(__fsub_rn(ix2, ix1), 0.0f);
                const float ih  = fmaxf(__fsub_rn(iy2, iy1), 0.0f);
                const float inter = __fmul_rn(iw, ih);
                const float a1  = __fmul_rn(__fsub_rn(wbx.z, wbx.x), __fsub_rn(wbx.w, wbx.y));
                const float a2  = __fmul_rn(__fsub_rn(ab.z,  ab.x),  __fsub_rn(ab.w,  ab.y));
                const float uni = __fsub_rn(__fadd_rn(a1, a2), inter);
                if (uni > 0.0f && __fdiv_rn(inter, uni) > IOU_TH) sup = true;
            }
            sup = (__ballot_sync(0xffffffffu, sup) != 0u);

            if (!sup) {
                if (lane == t) {           // owner lane writes
                    abox[acc] = bx;
                    float* o = out + ((size_t)b * TOPK + acc) * 6;
                    o[0] = cl;
                    o[1] = __uint_as_float((u32)(k >> 32) ^ 0x80000000u);
                    o[2] = bx.x; o[3] = bx.y; o[4] = bx.z; o[5] = bx.w;
                }
                acc++;
            }
            __syncwarp();
        }
    }

    // ---- exactness fallback: tournament over chunk tails (rare) ----
    if (acc < TOPK && !exhausted) {
        int p0 = 0, e0 = 0;
        u64 k0 = 0;
        float4 b0 = make_float4(0.f, 0.f, 0.f, 0.f);
        float  c0 = 0.f;
        if (lane < NCHUNK) {
            p0 = lane * CHSZ + chunkcnt[lane];
            e0 = (lane + 1) * CHSZ;
            k0 = (p0 < e0) ? __ldg(&gk[p0]) : 0ull;
            if (k0) { const int a_ = (int)(0xFFFFFFFFu - (u32)k0);
                      b0 = __ldg(&gb[a_]); c0 = __ldg(&gc[a_]); }
        }
        while (acc < TOPK) {
            const u32 hi = (u32)(k0 >> 32);
            const u32 mh = __reduce_max_sync(0xffffffffu, hi);
            const u32 lo = (hi == mh) ? (u32)k0 : 0u;
            const u32 ml = __reduce_max_sync(0xffffffffu, lo);
            if (mh == 0u) break;

            const bool iwin = (hi == mh) && ((u32)k0 == ml);
            const u32  wb   = __ballot_sync(0xffffffffu, iwin);
            const int  wl   = __ffs(wb) - 1;

            float4 wbx;
            wbx.x = __shfl_sync(0xffffffffu, b0.x, wl);
            wbx.y = __shfl_sync(0xffffffffu, b0.y, wl);
            wbx.z = __shfl_sync(0xffffffffu, b0.z, wl);
            wbx.w = __shfl_sync(0xffffffffu, b0.w, wl);
            const float wcls = __shfl_sync(0xffffffffu, c0, wl);

            bool sup = false;
            for (int a = lane; a < acc; a += 32) {
                const float4 ab = abox[a];
                const float ix1 = fmaxf(wbx.x, ab.x);
                const float iy1 = fmaxf(wbx.y, ab.y);
                const float ix2 = fminf(wbx.z, ab.z);
                const float iy2 = fminf(wbx.w, ab.w);
                const float iw  = fmaxf(__fsub_rn(ix2, ix1), 0.0f);
                const float ih  = fmaxf(__fsub_rn(iy2, iy1), 0.0f);
                const float inter = __fmul_rn(iw, ih);
                const float a1  = __fmul_rn(__fsub_rn(wbx.z, wbx.x), __fsub_rn(wbx.w, wbx.y));
                const float a2  = __fmul_rn(__fsub_rn(ab.z,  ab.x),  __fsub_rn(ab.w,  ab.y));
                const float uni = __fsub_rn(__fadd_rn(a1, a2), inter);
                if (uni > 0.0f && __fdiv_rn(inter, uni) > IOU_TH) sup = true;
            }
            sup = (__ballot_sync(0xffffffffu, sup) != 0u);

            if (!sup) {
                if (lane == wl) {
                    abox[acc] = wbx;
                    float* o = out + ((size_t)b * TOPK + acc) * 6;
                    o[0] = wcls;
                    o[1] = __uint_as_float(mh ^ 0x80000000u);
                    o[2] = wbx.x; o[3] = wbx.y; o[4] = wbx.z; o[5] = wbx.w;
                }
                acc++;
            }

            if (iwin) {
                p0++;
                k0 = (p0 < e0) ? __ldg(&gk[p0]) : 0ull;
                if (k0) { const int a_ = (int)(0xFFFFFFFFu - (u32)k0);
                          b0 = __ldg(&gb[a_]); c0 = __ldg(&gc[a_]); }
            }
            __syncwarp();
        }
    }
}

// ---------------------------------------------------------------------------
extern "C" void kernel_launch(void* const* d_in, const int* in_sizes, int n_in,
                              void* d_out, int out_size)
{
    const float* y   = (const float*)d_in[0];
    float*       out = (float*)d_out;

    // decode: 64 anchors per 256-thread CTA
    const int dec_smem = 64 * NCH * 4;    // 23808 B
    cudaFuncSetAttribute(decode_kernel,
                         cudaFuncAttributeMaxDynamicSharedMemorySize, dec_smem);
    dim3 dgrid((NA + 63) / 64, NB);
    decode_kernel<<<dgrid, 256, dec_smem>>>(y);

    // chunk sort: 384 CTAs
    const int sort_smem = CHSZ * 8;       // 16384 B
    cudaFuncSetAttribute(sort_kernel,
                         cudaFuncAttributeMaxDynamicSharedMemorySize, sort_smem);
    dim3 sgrid(NCHUNK, NB);
    sort_kernel<<<sgrid, 1024, sort_smem>>>();

    // merge-select + walk: one CTA per batch
    const int nms_smem = (NCHUNK * SSEL + SSEL) * 8 + TOPK * 16 + NCHUNK * 4;
    cudaFuncSetAttribute(nms_kernel,
                         cudaFuncAttributeMaxDynamicSharedMemorySize, nms_smem);
    nms_kernel<<<NB, 1024, nms_smem>>>(out);
}

// round 6
// speedup vs baseline: 1.9100x; 1.0667x over previous
#include <cuda_runtime.h>
#include <math.h>

#define NA     24564          // anchors per batch
#define NAP    24576          // padded to 24*1024
#define NB     32             // batch
#define NCH    93
#define TOPK   200
#define CONF_TH 0.01f
#define IOU_TH  0.45f
#define CANDN  1024           // max selected candidates
#define SELTGT 512            // selection target

typedef unsigned long long u64;
typedef unsigned int u32;

// scratch (device globals: no allocation allowed; zero-initialized, and the
// [NA, NAP) pad of g_keys is never written -> stays 0)
__device__ u64    g_keys [NB * NAP];   // mono(conf)<<32 | (~anchor); 0 if invalid
__device__ float4 g_boxes[NB * NAP];
__device__ float  g_cls  [NB * NAP];

// ---------------------------------------------------------------------------
// Kernel 1: decode. 256 threads / 64 anchors -> 23.8KB SMEM, 8 CTAs/SM.
// ---------------------------------------------------------------------------
__global__ void __launch_bounds__(256) decode_kernel(const float* __restrict__ y)
{
    extern __shared__ float smF[];        // 64*93 floats
    const int b   = blockIdx.y;
    const int a0  = blockIdx.x * 64;
    const int cnt = min(64, NA - a0);
    const int tid = threadIdx.x;

    const float* base = y + ((size_t)b * NA + a0) * NCH;
    const int nvec = (cnt * NCH) >> 2;    // cnt multiple of 4
    const float4* b4 = (const float4*)base;
    float4* s4 = (float4*)smF;
    #pragma unroll 2
    for (int i = tid; i < nvec; i += 256) s4[i] = b4[i];
    __syncthreads();

    if (tid >= cnt) return;
    const float* r = smF + tid * NCH;     // stride 93 (odd) -> conflict-free

    float best = r[0]; int bi = 0;
    #pragma unroll
    for (int c = 1; c < 81; c++) {
        const float v = r[c];
        if (v > best) { best = v; bi = c; }   // first-max => lowest index
    }

    const float y81 = r[81], y82 = r[82], y83 = r[83], y84 = r[84];
    const float y85 = r[85], y86 = r[86], y87 = r[87], y88 = r[88];
    const float y89 = r[89], y90 = r[90], y91 = r[91], y92 = r[92];

    const float cx = y81 * y89 * y87 + y85;
    const float cy = y82 * y90 * y88 + y86;
    const float w  = expf(y83 * y91) * y87;
    const float h  = expf(y84 * y92) * y88;

    float4 box;
    box.x = (cx - 0.5f * w) * 512.0f;
    box.y = (cy - 0.5f * h) * 512.0f;
    box.z = (cx + 0.5f * w) * 512.0f;
    box.w = (cy + 0.5f * h) * 512.0f;

    const int  anchor = a0 + tid;
    const int  idx    = b * NAP + anchor;
    const bool valid  = (bi != 0) && (best > CONF_TH);
    const u32  mono   = __float_as_uint(best) | 0x80000000u;  // best>0
    g_keys [idx] = valid ? (((u64)mono << 32) | (u64)(0xFFFFFFFFu - (u32)anchor))
                         : 0ull;
    g_boxes[idx] = box;
    g_cls  [idx] = (float)bi;
}

// ---------------------------------------------------------------------------
// Kernel 2: radix-select + sort + walk. One CTA (1024 thr) per batch.
// ---------------------------------------------------------------------------
__global__ void __launch_bounds__(1024, 1) nms_kernel(float* __restrict__ out)
{
    // small static shared
    __shared__ u32 hist[256];
    __shared__ u64 sh_prefix;
    __shared__ u64 sh_pv;
    __shared__ u32 sh_A;
    __shared__ int sh_break;
    __shared__ int sh_cnt;

    extern __shared__ u64 smW[];
    u64*    skeys = smW;                      // NAP keys       (196608 B)
    u64*    cand  = smW + NAP;                // 1024 keys      (8192 B)
    float4* cbox  = (float4*)(cand + CANDN);  // 1024 boxes     (16384 B)
    float*  ccls  = (float*)(cbox + CANDN);   // 1024 classes   (4096 B)
    float4* abox  = (float4*)(ccls + CANDN);  // 200 accepted   (3200 B)

    const int b    = blockIdx.x;
    const int tid  = threadIdx.x;
    const int lane = tid & 31;
    const u64* gk  = g_keys + (size_t)b * NAP;

    // zero output slab + init
    for (int j = tid; j < TOPK * 6; j += 1024)
        out[b * TOPK * 6 + j] = 0.0f;
    cand[tid] = 0ull;
    if (tid == 0) { sh_prefix = 0; sh_pv = 0; sh_A = 0; sh_break = 0; sh_cnt = 0; }

    // stage keys in SMEM (pad of g_keys is guaranteed 0)
    #pragma unroll
    for (int it = 0; it < NAP / 1024; it++)
        skeys[tid + it * 1024] = gk[tid + it * 1024];
    __syncthreads();

    // ---- exact MSB radix select: find pv with count(key >= pv) in [512,1024]
    for (int r = 0; r < 8; r++) {
        if (tid < 256) hist[tid] = 0;
        __syncthreads();
        const u64 prefix  = sh_prefix;
        const int shift_d = 56 - 8 * r;

        #pragma unroll
        for (int it = 0; it < NAP / 1024; it++) {
            const u64 k = skeys[tid + it * 1024];
            bool active;
            if (r == 0) active = (k != 0ull);
            else        active = ((k >> (64 - 8 * r)) == prefix);
            const u32 dg = active ? (u32)((k >> shift_d) & 255u) : (300u + lane);
            const u32 m  = __match_any_sync(0xffffffffu, dg);
            if (active && ((m & ((1u << lane) - 1u)) == 0u))
                atomicAdd(&hist[dg], (u32)__popc(m));
        }
        __syncthreads();

        if (tid == 0) {
            const u32 A = sh_A;
            int d = 255; u32 c = 0;
            for (; d >= 0; d--) { c += hist[d]; if (A + c >= SELTGT) break; }
            if (d < 0) {                     // fewer than SELTGT keys total
                sh_break = 1;
                sh_pv = (r == 0) ? 0ull : (sh_prefix << (64 - 8 * r));
            } else {
                const u32 abv = A + c - hist[d];
                const u64 np  = (sh_prefix << 8) | (u64)(u32)d;
                if (abv + hist[d] <= CANDN || r == 7) {
                    sh_break = 1;
                    sh_pv = np << (56 - 8 * r);
                } else {
                    sh_prefix = np;
                    sh_A = abv;
                }
            }
        }
        __syncthreads();
        if (sh_break) break;
    }
    u64 pv = sh_pv;
    if (pv == 0ull) pv = 1ull;               // exclude invalid keys

    // ---- compaction (ballot-aggregated append) ----
    #pragma unroll
    for (int it = 0; it < NAP / 1024; it++) {
        const u64 k = skeys[tid + it * 1024];
        const bool sel = (k >= pv);
        const u32 bal = __ballot_sync(0xffffffffu, sel);
        if (bal) {
            const int ldr = __ffs(bal) - 1;
            u32 base = 0;
            if (lane == ldr) base = (u32)atomicAdd(&sh_cnt, __popc(bal));
            base = __shfl_sync(0xffffffffu, base, ldr);
            if (sel) cand[base + __popc(bal & ((1u << lane) - 1u))] = k;
        }
    }
    __syncthreads();

    // ---- bitonic sort CANDN keys descending (zeros pad to the end) ----
    for (int kk = 2; kk <= CANDN; kk <<= 1) {
        for (int j = kk >> 1; j; j >>= 1) {
            __syncthreads();
            if (tid < CANDN / 2) {
                const int t = ((tid & ~(j - 1)) << 1) | (tid & (j - 1));
                const int p = t | j;
                const u64 A = cand[t];
                const u64 B = cand[p];
                const bool desc = ((t & kk) == 0);
                if (desc ? (A < B) : (A > B)) { cand[t] = B; cand[p] = A; }
            }
        }
    }
    __syncthreads();

    // ---- gather candidate boxes/classes into SMEM ----
    const int cnt = sh_cnt;
    if (tid < cnt) {
        const u64 k  = cand[tid];
        const int a_ = (int)(0xFFFFFFFFu - (u32)k);
        cbox[tid] = g_boxes[(size_t)b * NAP + a_];
        ccls[tid] = g_cls  [(size_t)b * NAP + a_];
    }
    __syncthreads();
    if (tid >= 32) return;                    // warp 0 only

    const float4* gb = g_boxes + (size_t)b * NAP;
    const float*  gc = g_cls   + (size_t)b * NAP;

    int acc = 0;

    // ---- main walk over sorted candidates (all data in SMEM) ----
    for (int i = 0; i < cnt && acc < TOPK; i++) {
        const float4 w = cbox[i];             // broadcast LDS

        bool sup = false;
        for (int a = lane; a < acc; a += 32) {
            const float4 ab = abox[a];
            const float ix1 = fmaxf(w.x, ab.x);
            const float iy1 = fmaxf(w.y, ab.y);
            const float ix2 = fminf(w.z, ab.z);
            const float iy2 = fminf(w.w, ab.w);
            const float iw  = fmaxf(__fsub_rn(ix2, ix1), 0.0f);
            const float ih  = fmaxf(__fsub_rn(iy2, iy1), 0.0f);
            const float inter = __fmul_rn(iw, ih);
            const float a1  = __fmul_rn(__fsub_rn(w.z, w.x), __fsub_rn(w.w, w.y));
            const float a2  = __fmul_rn(__fsub_rn(ab.z, ab.x), __fsub_rn(ab.w, ab.y));
            const float uni = __fsub_rn(__fadd_rn(a1, a2), inter);
            if (uni > 0.0f && __fdiv_rn(inter, uni) > IOU_TH) sup = true;
        }
        sup = (__ballot_sync(0xffffffffu, sup) != 0u);

        if (!sup) {
            if (lane == 0) {
                abox[acc] = w;
                const u64 k = cand[i];
                float* o = out + ((size_t)b * TOPK + acc) * 6;
                o[0] = ccls[i];
                o[1] = __uint_as_float((u32)(k >> 32) ^ 0x80000000u);
                o[2] = w.x; o[3] = w.y; o[4] = w.z; o[5] = w.w;
            }
            acc++;
        }
        __syncwarp();
    }

    // ---- exactness fallback: pop keys < pv in descending order (rare) ----
    if (acc < TOPK) {
        u64 last = pv;
        while (acc < TOPK) {
            u64 best = 0ull;
            for (int j = lane; j < NAP; j += 32) {
                const u64 k = skeys[j];
                if (k < last && k > best) best = k;
            }
            const u32 hi = (u32)(best >> 32);
            const u32 mh = __reduce_max_sync(0xffffffffu, hi);
            const u32 lo = (hi == mh) ? (u32)best : 0u;
            const u32 ml = __reduce_max_sync(0xffffffffu, lo);
            if (mh == 0u) break;
            const u64 wkey = ((u64)mh << 32) | (u64)ml;
            const int a_   = (int)(0xFFFFFFFFu - ml);

            float4 w;
            if (lane == 0) w = __ldg(&gb[a_]);
            w.x = __shfl_sync(0xffffffffu, w.x, 0);
            w.y = __shfl_sync(0xffffffffu, w.y, 0);
            w.z = __shfl_sync(0xffffffffu, w.z, 0);
            w.w = __shfl_sync(0xffffffffu, w.w, 0);

            bool sup = false;
            for (int a = lane; a < acc; a += 32) {
                const float4 ab = abox[a];
                const float ix1 = fmaxf(w.x, ab.x);
                const float iy1 = fmaxf(w.y, ab.y);
                const float ix2 = fminf(w.z, ab.z);
                const float iy2 = fminf(w.w, ab.w);
                const float iw  = fmaxf(__fsub_rn(ix2, ix1), 0.0f);
                const float ih  = fmaxf(__fsub_rn(iy2, iy1), 0.0f);
                const float inter = __fmul_rn(iw, ih);
                const float a1  = __fmul_rn(__fsub_rn(w.z, w.x), __fsub_rn(w.w, w.y));
                const float a2  = __fmul_rn(__fsub_rn(ab.z, ab.x), __fsub_rn(ab.w, ab.y));
                const float uni = __fsub_rn(__fadd_rn(a1, a2), inter);
                if (uni > 0.0f && __fdiv_rn(inter, uni) > IOU_TH) sup = true;
            }
            sup = (__ballot_sync(0xffffffffu, sup) != 0u);

            if (!sup) {
                if (lane == 0) {
                    abox[acc] = w;
                    float* o = out + ((size_t)b * TOPK + acc) * 6;
                    o[0] = __ldg(&gc[a_]);
                    o[1] = __uint_as_float(mh ^ 0x80000000u);
                    o[2] = w.x; o[3] = w.y; o[4] = w.z; o[5] = w.w;
                }
                acc++;
            }
            last = wkey;
            __syncwarp();
        }
    }
}

// ---------------------------------------------------------------------------
extern "C" void kernel_launch(void* const* d_in, const int* in_sizes, int n_in,
                              void* d_out, int out_size)
{
    const float* y   = (const float*)d_in[0];
    float*       out = (float*)d_out;

    // decode: 64 anchors per 256-thread CTA
    const int dec_smem = 64 * NCH * 4;    // 23808 B
    cudaFuncSetAttribute(decode_kernel,
                         cudaFuncAttributeMaxDynamicSharedMemorySize, dec_smem);
    dim3 dgrid((NA + 63) / 64, NB);
    decode_kernel<<<dgrid, 256, dec_smem>>>(y);

    // select + sort + walk: one CTA per batch
    const int nms_smem = NAP * 8            // keys
                       + CANDN * 8          // cand
                       + CANDN * 16         // cbox
                       + CANDN * 4          // ccls
                       + TOPK * 16;         // abox   = 228480 B
    cudaFuncSetAttribute(nms_kernel,
                         cudaFuncAttributeMaxDynamicSharedMemorySize, nms_smem);
    nms_kernel<<<NB, 1024, nms_smem>>>(out);
}

// round 7
// speedup vs baseline: 4.5518x; 2.3832x over previous
#include <cuda_runtime.h>
#include <math.h>

#define NA     24564          // anchors per batch
#define NAP    24576          // padded to 24*1024
#define NB     32             // batch
#define NCH    93
#define TOPK   200
#define CONF_TH 0.01f
#define IOU_TH  0.45f
#define CANDN  1024           // max selected candidates
#define SELTGT 512            // selection target

typedef unsigned long long u64;
typedef unsigned int u32;

// scratch (device globals: no allocation allowed; zero-initialized, and the
// [NA, NAP) pad of g_keys is never written -> stays 0)
__device__ u64    g_keys [NB * NAP];   // mono(conf)<<32 | (~anchor); 0 if invalid
__device__ float4 g_boxes[NB * NAP];
__device__ float  g_cls  [NB * NAP];

// ---------------------------------------------------------------------------
// Kernel 1: decode. 256 threads / 64 anchors -> 23.8KB SMEM, 8 CTAs/SM.
// ---------------------------------------------------------------------------
__global__ void __launch_bounds__(256) decode_kernel(const float* __restrict__ y)
{
    extern __shared__ float smF[];        // 64*93 floats
    const int b   = blockIdx.y;
    const int a0  = blockIdx.x * 64;
    const int cnt = min(64, NA - a0);
    const int tid = threadIdx.x;

    const float* base = y + ((size_t)b * NA + a0) * NCH;
    const int nvec = (cnt * NCH) >> 2;    // cnt multiple of 4
    const float4* b4 = (const float4*)base;
    float4* s4 = (float4*)smF;
    #pragma unroll 2
    for (int i = tid; i < nvec; i += 256) s4[i] = b4[i];
    __syncthreads();

    if (tid >= cnt) return;
    const float* r = smF + tid * NCH;     // stride 93 (odd) -> conflict-free

    float best = r[0]; int bi = 0;
    #pragma unroll
    for (int c = 1; c < 81; c++) {
        const float v = r[c];
        if (v > best) { best = v; bi = c; }   // first-max => lowest index
    }

    const float y81 = r[81], y82 = r[82], y83 = r[83], y84 = r[84];
    const float y85 = r[85], y86 = r[86], y87 = r[87], y88 = r[88];
    const float y89 = r[89], y90 = r[90], y91 = r[91], y92 = r[92];

    const float cx = y81 * y89 * y87 + y85;
    const float cy = y82 * y90 * y88 + y86;
    const float w  = expf(y83 * y91) * y87;
    const float h  = expf(y84 * y92) * y88;

    float4 box;
    box.x = (cx - 0.5f * w) * 512.0f;
    box.y = (cy - 0.5f * h) * 512.0f;
    box.z = (cx + 0.5f * w) * 512.0f;
    box.w = (cy + 0.5f * h) * 512.0f;

    const int  anchor = a0 + tid;
    const int  idx    = b * NAP + anchor;
    const bool valid  = (bi != 0) && (best > CONF_TH);
    const u32  mono   = __float_as_uint(best) | 0x80000000u;  // best>0
    g_keys [idx] = valid ? (((u64)mono << 32) | (u64)(0xFFFFFFFFu - (u32)anchor))
                         : 0ull;
    g_boxes[idx] = box;
    g_cls  [idx] = (float)bi;
}

// ---------------------------------------------------------------------------
// IoU > thresh test, rounding-exact (no FMA contraction), operand order:
// a1 = area(w) [candidate], a2 = area(ab) [earlier box].
// ---------------------------------------------------------------------------
__device__ __forceinline__ bool iou_gt(const float4 w, const float4 ab)
{
    const float ix1 = fmaxf(w.x, ab.x);
    const float iy1 = fmaxf(w.y, ab.y);
    const float ix2 = fminf(w.z, ab.z);
    const float iy2 = fminf(w.w, ab.w);
    const float iw  = fmaxf(__fsub_rn(ix2, ix1), 0.0f);
    const float ih  = fmaxf(__fsub_rn(iy2, iy1), 0.0f);
    const float inter = __fmul_rn(iw, ih);
    const float a1  = __fmul_rn(__fsub_rn(w.z, w.x), __fsub_rn(w.w, w.y));
    const float a2  = __fmul_rn(__fsub_rn(ab.z, ab.x), __fsub_rn(ab.w, ab.y));
    const float uni = __fsub_rn(__fadd_rn(a1, a2), inter);
    return (uni > 0.0f) && (__fdiv_rn(inter, uni) > IOU_TH);
}

// ---------------------------------------------------------------------------
// Kernel 2: radix-select + sort + wave-parallel walk. One CTA per batch.
// ---------------------------------------------------------------------------
__global__ void __launch_bounds__(1024, 1) nms_kernel(float* __restrict__ out)
{
    __shared__ u32 hist[256];
    __shared__ u64 sh_prefix;
    __shared__ u64 sh_pv;
    __shared__ u32 sh_A;
    __shared__ int sh_break;
    __shared__ int sh_cnt;
    __shared__ u32 wv_sup [32];     // per-wave: suppressed-by-accepted flags
    __shared__ u32 wv_mask[32];     // per-wave: intra-wave overlap masks

    extern __shared__ u64 smW[];
    u64*    skeys = smW;                      // NAP keys       (196608 B)
    u64*    cand  = smW + NAP;                // 1024 keys      (8192 B)
    float4* cbox  = (float4*)(cand + CANDN);  // 1024 boxes     (16384 B)
    float*  ccls  = (float*)(cbox + CANDN);   // 1024 classes   (4096 B)
    float4* abox  = (float4*)(ccls + CANDN);  // 200 accepted   (3200 B)

    const int b    = blockIdx.x;
    const int tid  = threadIdx.x;
    const int lane = tid & 31;
    const int wid  = tid >> 5;
    const u64* gk  = g_keys + (size_t)b * NAP;

    for (int j = tid; j < TOPK * 6; j += 1024)
        out[b * TOPK * 6 + j] = 0.0f;
    cand[tid] = 0ull;
    if (tid == 0) { sh_prefix = 0; sh_pv = 0; sh_A = 0; sh_break = 0; sh_cnt = 0; }

    // stage keys in SMEM (pad of g_keys is guaranteed 0)
    #pragma unroll
    for (int it = 0; it < NAP / 1024; it++)
        skeys[tid + it * 1024] = gk[tid + it * 1024];
    __syncthreads();

    // ---- exact MSB radix select: find pv with count(key >= pv) in [512,1024]
    for (int r = 0; r < 8; r++) {
        if (tid < 256) hist[tid] = 0;
        __syncthreads();
        const u64 prefix  = sh_prefix;
        const int shift_d = 56 - 8 * r;

        #pragma unroll
        for (int it = 0; it < NAP / 1024; it++) {
            const u64 k = skeys[tid + it * 1024];
            bool active;
            if (r == 0) active = (k != 0ull);
            else        active = ((k >> (64 - 8 * r)) == prefix);
            const u32 dg = active ? (u32)((k >> shift_d) & 255u) : (300u + lane);
            const u32 m  = __match_any_sync(0xffffffffu, dg);
            if (active && ((m & ((1u << lane) - 1u)) == 0u))
                atomicAdd(&hist[dg], (u32)__popc(m));
        }
        __syncthreads();

        if (tid == 0) {
            const u32 A = sh_A;
            int d = 255; u32 c = 0;
            for (; d >= 0; d--) { c += hist[d]; if (A + c >= SELTGT) break; }
            if (d < 0) {
                sh_break = 1;
                sh_pv = (r == 0) ? 0ull : (sh_prefix << (64 - 8 * r));
            } else {
                const u32 abv = A + c - hist[d];
                const u64 np  = (sh_prefix << 8) | (u64)(u32)d;
                if (abv + hist[d] <= CANDN || r == 7) {
                    sh_break = 1;
                    sh_pv = np << (56 - 8 * r);
                } else {
                    sh_prefix = np;
                    sh_A = abv;
                }
            }
        }
        __syncthreads();
        if (sh_break) break;
    }
    u64 pv = sh_pv;
    if (pv == 0ull) pv = 1ull;               // exclude invalid keys

    // ---- compaction (ballot-aggregated append) ----
    #pragma unroll
    for (int it = 0; it < NAP / 1024; it++) {
        const u64 k = skeys[tid + it * 1024];
        const bool sel = (k >= pv);
        const u32 bal = __ballot_sync(0xffffffffu, sel);
        if (bal) {
            const int ldr = __ffs(bal) - 1;
            u32 base = 0;
            if (lane == ldr) base = (u32)atomicAdd(&sh_cnt, __popc(bal));
            base = __shfl_sync(0xffffffffu, base, ldr);
            if (sel) cand[base + __popc(bal & ((1u << lane) - 1u))] = k;
        }
    }
    __syncthreads();

    // ---- bitonic sort CANDN keys descending (zeros pad to the end) ----
    for (int kk = 2; kk <= CANDN; kk <<= 1) {
        for (int j = kk >> 1; j; j >>= 1) {
            __syncthreads();
            if (tid < CANDN / 2) {
                const int t = ((tid & ~(j - 1)) << 1) | (tid & (j - 1));
                const int p = t | j;
                const u64 A = cand[t];
                const u64 B = cand[p];
                const bool desc = ((t & kk) == 0);
                if (desc ? (A < B) : (A > B)) { cand[t] = B; cand[p] = A; }
            }
        }
    }
    __syncthreads();

    // ---- gather candidate boxes/classes into SMEM ----
    const int cnt = sh_cnt;
    if (tid < cnt) {
        const u64 k  = cand[tid];
        const int a_ = (int)(0xFFFFFFFFu - (u32)k);
        cbox[tid] = g_boxes[(size_t)b * NAP + a_];
        ccls[tid] = g_cls  [(size_t)b * NAP + a_];
    }
    __syncthreads();

    // ---- wave-parallel walk: 32 candidates per wave, one per warp ----
    int acc = 0;
    for (int base = 0; base < cnt && acc < TOPK; base += 32) {
        const int  c     = base + wid;
        const bool haveC = (c < cnt);

        float4 w = make_float4(0.f, 0.f, 0.f, 0.f);
        if (haveC) w = cbox[c];               // warp-uniform broadcast LDS

        // vs accepted set (lanes stride)
        bool sA = false;
        if (haveC)
            for (int a = lane; a < acc; a += 32)
                if (iou_gt(w, abox[a])) sA = true;
        const bool supA = (__ballot_sync(0xffffffffu, sA) != 0u);

        // intra-wave: lane i tests candidate (base+i) against this warp's cand
        bool ov = false;
        if (haveC && lane < wid)
            ov = iou_gt(w, cbox[base + lane]);
        const u32 m = __ballot_sync(0xffffffffu, ov);

        if (lane == 0) {
            wv_sup [wid] = (haveC && !supA) ? 0u : 1u;
            wv_mask[wid] = m;
        }
        __syncthreads();

        // serial bit-DP, replicated in every thread (identical result)
        u32 alive = 0u;
        int newacc = acc;
        #pragma unroll
        for (int i = 0; i < 32; i++) {
            if (newacc >= TOPK) break;
            if (!wv_sup[i] && ((wv_mask[i] & alive) == 0u)) {
                alive |= (1u << i);
                newacc++;
            }
        }

        // append accepted candidates (warp whose bit is set writes its row)
        if ((alive >> wid) & 1u) {
            const int slot = acc + __popc(alive & ((1u << wid) - 1u));
            if (lane == 0) {
                abox[slot] = w;
                const u64 k = cand[c];
                float* o = out + ((size_t)b * TOPK + slot) * 6;
                o[0] = ccls[c];
                o[1] = __uint_as_float((u32)(k >> 32) ^ 0x80000000u);
                o[2] = w.x; o[3] = w.y; o[4] = w.z; o[5] = w.w;
            }
        }
        acc = newacc;
        __syncthreads();
    }

    if (tid >= 32) return;                    // fallback: warp 0 only (rare)

    const float4* gb = g_boxes + (size_t)b * NAP;
    const float*  gc = g_cls   + (size_t)b * NAP;

    // ---- exactness fallback: pop keys < pv in descending order ----
    if (acc < TOPK) {
        u64 last = pv;
        while (acc < TOPK) {
            u64 best = 0ull;
            for (int j = lane; j < NAP; j += 32) {
                const u64 k = skeys[j];
                if (k < last && k > best) best = k;
            }
            const u32 hi = (u32)(best >> 32);
            const u32 mh = __reduce_max_sync(0xffffffffu, hi);
            const u32 lo = (hi == mh) ? (u32)best : 0u;
            const u32 ml = __reduce_max_sync(0xffffffffu, lo);
            if (mh == 0u) break;
            const u64 wkey = ((u64)mh << 32) | (u64)ml;
            const int a_   = (int)(0xFFFFFFFFu - ml);

            float4 w;
            if (lane == 0) w = __ldg(&gb[a_]);
            w.x = __shfl_sync(0xffffffffu, w.x, 0);
            w.y = __shfl_sync(0xffffffffu, w.y, 0);
            w.z = __shfl_sync(0xffffffffu, w.z, 0);
            w.w = __shfl_sync(0xffffffffu, w.w, 0);

            bool sup = false;
            for (int a = lane; a < acc; a += 32)
                if (iou_gt(w, abox[a])) sup = true;
            sup = (__ballot_sync(0xffffffffu, sup) != 0u);

            if (!sup) {
                if (lane == 0) {
                    abox[acc] = w;
                    float* o = out + ((size_t)b * TOPK + acc) * 6;
                    o[0] = __ldg(&gc[a_]);
                    o[1] = __uint_as_float(mh ^ 0x80000000u);
                    o[2] = w.x; o[3] = w.y; o[4] = w.z; o[5] = w.w;
                }
                acc++;
            }
            last = wkey;
            __syncwarp();
        }
    }
}

// ---------------------------------------------------------------------------
extern "C" void kernel_launch(void* const* d_in, const int* in_sizes, int n_in,
                              void* d_out, int out_size)
{
    const float* y   = (const float*)d_in[0];
    float*       out = (float*)d_out;

    // decode: 64 anchors per 256-thread CTA
    const int dec_smem = 64 * NCH * 4;    // 23808 B
    cudaFuncSetAttribute(decode_kernel,
                         cudaFuncAttributeMaxDynamicSharedMemorySize, dec_smem);
    dim3 dgrid((NA + 63) / 64, NB);
    decode_kernel<<<dgrid, 256, dec_smem>>>(y);

    // select + sort + wave walk: one CTA per batch
    const int nms_smem = NAP * 8 + CANDN * 8 + CANDN * 16 + CANDN * 4
                       + TOPK * 16;       // 228480 B
    cudaFuncSetAttribute(nms_kernel,
                         cudaFuncAttributeMaxDynamicSharedMemorySize, nms_smem);
    nms_kernel<<<NB, 1024, nms_smem>>>(out);
}

// round 8
// speedup vs baseline: 5.4085x; 1.1882x over previous
#include <cuda_runtime.h>
#include <math.h>

#define NA     24564          // anchors per batch
#define NAP    24576          // padded to 24*1024
#define NB     32             // batch
#define NCH    93
#define TOPK   200
#define CONF_TH 0.01f
#define IOU_TH  0.45f
#define CANDN  1024           // max selected candidates
#define SELTGT 512            // selection target

typedef unsigned long long u64;
typedef unsigned int u32;

// scratch (device globals: no allocation allowed; zero-initialized, and the
// [NA, NAP) pad of g_keys is never written -> stays 0)
__device__ u64    g_keys [NB * NAP];   // mono(conf)<<32 | (~anchor); 0 if invalid
__device__ float4 g_boxes[NB * NAP];
__device__ float  g_cls  [NB * NAP];

// ---------------------------------------------------------------------------
// Kernel 1: decode. 256 threads / 64 anchors -> 23.8KB SMEM, 8 CTAs/SM.
// ---------------------------------------------------------------------------
__global__ void __launch_bounds__(256) decode_kernel(const float* __restrict__ y)
{
    extern __shared__ float smF[];        // 64*93 floats
    const int b   = blockIdx.y;
    const int a0  = blockIdx.x * 64;
    const int cnt = min(64, NA - a0);
    const int tid = threadIdx.x;

    const float* base = y + ((size_t)b * NA + a0) * NCH;
    const int nvec = (cnt * NCH) >> 2;
    const float4* b4 = (const float4*)base;
    float4* s4 = (float4*)smF;
    #pragma unroll 2
    for (int i = tid; i < nvec; i += 256) s4[i] = b4[i];
    __syncthreads();

    if (tid >= cnt) return;
    const float* r = smF + tid * NCH;     // stride 93 (odd) -> conflict-free

    float best = r[0]; int bi = 0;
    #pragma unroll
    for (int c = 1; c < 81; c++) {
        const float v = r[c];
        if (v > best) { best = v; bi = c; }   // first-max => lowest index
    }

    const float y81 = r[81], y82 = r[82], y83 = r[83], y84 = r[84];
    const float y85 = r[85], y86 = r[86], y87 = r[87], y88 = r[88];
    const float y89 = r[89], y90 = r[90], y91 = r[91], y92 = r[92];

    const float cx = y81 * y89 * y87 + y85;
    const float cy = y82 * y90 * y88 + y86;
    const float w  = expf(y83 * y91) * y87;
    const float h  = expf(y84 * y92) * y88;

    float4 box;
    box.x = (cx - 0.5f * w) * 512.0f;
    box.y = (cy - 0.5f * h) * 512.0f;
    box.z = (cx + 0.5f * w) * 512.0f;
    box.w = (cy + 0.5f * h) * 512.0f;

    const int  anchor = a0 + tid;
    const int  idx    = b * NAP + anchor;
    const bool valid  = (bi != 0) && (best > CONF_TH);
    const u32  mono   = __float_as_uint(best) | 0x80000000u;
    g_keys [idx] = valid ? (((u64)mono << 32) | (u64)(0xFFFFFFFFu - (u32)anchor))
                         : 0ull;
    g_boxes[idx] = box;
    g_cls  [idx] = (float)bi;
}

// ---------------------------------------------------------------------------
__device__ __forceinline__ bool iou_gt(const float4 w, const float4 ab)
{
    const float ix1 = fmaxf(w.x, ab.x);
    const float iy1 = fmaxf(w.y, ab.y);
    const float ix2 = fminf(w.z, ab.z);
    const float iy2 = fminf(w.w, ab.w);
    const float iw  = fmaxf(__fsub_rn(ix2, ix1), 0.0f);
    const float ih  = fmaxf(__fsub_rn(iy2, iy1), 0.0f);
    const float inter = __fmul_rn(iw, ih);
    const float a1  = __fmul_rn(__fsub_rn(w.z, w.x), __fsub_rn(w.w, w.y));
    const float a2  = __fmul_rn(__fsub_rn(ab.z, ab.x), __fsub_rn(ab.w, ab.y));
    const float uni = __fsub_rn(__fadd_rn(a1, a2), inter);
    return (uni > 0.0f) && (__fdiv_rn(inter, uni) > IOU_TH);
}

// ---------------------------------------------------------------------------
// Kernel 2: 12-bit histogram select + hybrid bitonic sort + wave walk.
// One CTA (1024 thr) per batch. Keys read from global (L2-resident).
// ---------------------------------------------------------------------------
__global__ void __launch_bounds__(1024, 1) nms_kernel(float* __restrict__ out)
{
    __shared__ u32 hist[4096];
    __shared__ u32 seg[256];
    __shared__ u64 sh_prefix;
    __shared__ u64 sh_pv;
    __shared__ u32 sh_A;
    __shared__ int sh_break;
    __shared__ int sh_cnt;
    __shared__ u32 wv_sup [32];
    __shared__ u32 wv_mask[32];

    extern __shared__ u64 smW[];
    u64*    cand = smW;                       // 1024 keys   (8192 B)
    float4* cbox = (float4*)(cand + CANDN);   // 1024 boxes  (16384 B)
    float*  ccls = (float*)(cbox + CANDN);    // 1024 cls    (4096 B)
    float4* abox = (float4*)(ccls + CANDN);   // 200 accepted(3200 B)

    const int b    = blockIdx.x;
    const int tid  = threadIdx.x;
    const int lane = tid & 31;
    const int wid  = tid >> 5;
    const u64* gk  = g_keys + (size_t)b * NAP;

    for (int j = tid; j < TOPK * 6; j += 1024)
        out[b * TOPK * 6 + j] = 0.0f;
    cand[tid] = 0ull;
    if (tid == 0) { sh_prefix = 0; sh_pv = 0; sh_A = 0; sh_break = 0; sh_cnt = 0; }

    // ---- exact select via 12-bit-digit MSB histograms over global keys ----
    for (int level = 0; level < 5; level++) {
        const int shift = 52 - 12 * level;
        for (int i = tid; i < 4096; i += 1024) hist[i] = 0;
        __syncthreads();
        const u64 prefix = sh_prefix;

        #pragma unroll
        for (int it = 0; it < NAP / 1024; it++) {
            const u64 k = gk[tid + it * 1024];
            const bool active = (k != 0ull) &&
                (level == 0 || (k >> (shift + 12)) == prefix);
            if (active) atomicAdd(&hist[(u32)((k >> shift) & 4095u)], 1u);
        }
        __syncthreads();

        if (tid < 256) {
            u32 s = 0;
            #pragma unroll
            for (int i = 0; i < 16; i++) s += hist[tid * 16 + i];
            seg[tid] = s;
        }
        __syncthreads();

        if (tid == 0) {
            const u32 need = SELTGT - sh_A;
            u32 c = 0; int sgi = -1; u32 cAfter = 0;
            for (int s = 255; s >= 0; s--) {
                if (c + seg[s] >= need) { sgi = s; cAfter = c; break; }
                c += seg[s];
            }
            if (sgi < 0) {
                // fewer than SELTGT valid keys total: select all valid
                sh_pv = 1ull;
                sh_break = 1;
            } else {
                u32 c2 = cAfter; int d = sgi * 16; u32 hT = 0;
                for (int i = 15; i >= 0; i--) {
                    const u32 h = hist[sgi * 16 + i];
                    if (c2 + h >= need) { d = sgi * 16 + i; hT = h; break; }
                    c2 += h;
                }
                if (sh_A + c2 + hT <= CANDN || level == 4) {
                    sh_pv = ((prefix << 12) | (u64)(u32)d) << shift;
                    sh_break = 1;
                } else {
                    sh_prefix = (prefix << 12) | (u64)(u32)d;
                    sh_A += c2;
                }
            }
        }
        __syncthreads();
        if (sh_break) break;
    }
    u64 pv = sh_pv;
    if (pv == 0ull) pv = 1ull;

    // ---- compaction (ballot-aggregated append) ----
    #pragma unroll
    for (int it = 0; it < NAP / 1024; it++) {
        const u64 k = gk[tid + it * 1024];
        const bool sel = (k >= pv);
        const u32 bal = __ballot_sync(0xffffffffu, sel);
        if (bal) {
            const int ldr = __ffs(bal) - 1;
            u32 base = 0;
            if (lane == ldr) base = (u32)atomicAdd(&sh_cnt, __popc(bal));
            base = __shfl_sync(0xffffffffu, base, ldr);
            if (sel) cand[base + __popc(bal & ((1u << lane) - 1u))] = k;
        }
    }
    __syncthreads();

    // ---- hybrid bitonic sort, descending; zeros pad to the end ----
    {
        u64 v = cand[tid];
        // intra-warp phases k = 2..32 (j <= 16): registers + shuffles
        #pragma unroll
        for (int k = 2; k <= 32; k <<= 1) {
            const bool desc = ((tid & k) == 0);
            #pragma unroll
            for (int j = k >> 1; j >= 1; j >>= 1) {
                const u64 o = __shfl_xor_sync(0xffffffffu, v, j);
                const bool lower = ((tid & j) == 0);
                v = ((desc == lower) ? (v > o) : (v < o)) ? v : o;
            }
        }
        cand[tid] = v;

        for (int k = 64; k <= CANDN; k <<= 1) {
            // SMEM stages j = k/2 .. 32
            for (int j = k >> 1; j >= 32; j >>= 1) {
                __syncthreads();
                if (tid < CANDN / 2) {
                    const int t = ((tid & ~(j - 1)) << 1) | (tid & (j - 1));
                    const int p = t | j;
                    const u64 A = cand[t];
                    const u64 B = cand[p];
                    const bool desc = ((t & k) == 0);
                    if (desc ? (A < B) : (A > B)) { cand[t] = B; cand[p] = A; }
                }
            }
            __syncthreads();
            // register stages j = 16 .. 1
            v = cand[tid];
            const bool desc = ((tid & k) == 0);
            #pragma unroll
            for (int j = 16; j >= 1; j >>= 1) {
                const u64 o = __shfl_xor_sync(0xffffffffu, v, j);
                const bool lower = ((tid & j) == 0);
                v = ((desc == lower) ? (v > o) : (v < o)) ? v : o;
            }
            cand[tid] = v;
        }
        __syncthreads();
    }

    // ---- gather candidate boxes/classes into SMEM ----
    const int cnt = sh_cnt;
    if (tid < cnt) {
        const u64 k  = cand[tid];
        const int a_ = (int)(0xFFFFFFFFu - (u32)k);
        cbox[tid] = g_boxes[(size_t)b * NAP + a_];
        ccls[tid] = g_cls  [(size_t)b * NAP + a_];
    }
    __syncthreads();

    // ---- wave-parallel walk: 32 candidates per wave, one per warp ----
    int acc = 0;
    for (int base = 0; base < cnt && acc < TOPK; base += 32) {
        const int  c     = base + wid;
        const bool haveC = (c < cnt);

        float4 w = make_float4(0.f, 0.f, 0.f, 0.f);
        if (haveC) w = cbox[c];

        bool sA = false;
        if (haveC)
            for (int a = lane; a < acc; a += 32)
                if (iou_gt(w, abox[a])) sA = true;
        const bool supA = (__ballot_sync(0xffffffffu, sA) != 0u);

        bool ov = false;
        if (haveC && lane < wid)
            ov = iou_gt(w, cbox[base + lane]);
        const u32 m = __ballot_sync(0xffffffffu, ov);

        if (lane == 0) {
            wv_sup [wid] = (haveC && !supA) ? 0u : 1u;
            wv_mask[wid] = m;
        }
        __syncthreads();

        u32 alive = 0u;
        int newacc = acc;
        #pragma unroll
        for (int i = 0; i < 32; i++) {
            if (newacc >= TOPK) break;
            if (!wv_sup[i] && ((wv_mask[i] & alive) == 0u)) {
                alive |= (1u << i);
                newacc++;
            }
        }

        if ((alive >> wid) & 1u) {
            const int slot = acc + __popc(alive & ((1u << wid) - 1u));
            if (lane == 0) {
                abox[slot] = w;
                const u64 k = cand[c];
                float* o = out + ((size_t)b * TOPK + slot) * 6;
                o[0] = ccls[c];
                o[1] = __uint_as_float((u32)(k >> 32) ^ 0x80000000u);
                o[2] = w.x; o[3] = w.y; o[4] = w.z; o[5] = w.w;
            }
        }
        acc = newacc;
        __syncthreads();
    }

    if (tid >= 32) return;                    // fallback: warp 0 only (rare)

    const float4* gb = g_boxes + (size_t)b * NAP;
    const float*  gc = g_cls   + (size_t)b * NAP;

    // ---- exactness fallback: pop keys < pv in descending order ----
    if (acc < TOPK) {
        u64 last = pv;
        while (acc < TOPK) {
            u64 best = 0ull;
            for (int j = lane; j < NAP; j += 32) {
                const u64 k = gk[j];
                if (k < last && k > best) best = k;
            }
            const u32 hi = (u32)(best >> 32);
            const u32 mh = __reduce_max_sync(0xffffffffu, hi);
            const u32 lo = (hi == mh) ? (u32)best : 0u;
            const u32 ml = __reduce_max_sync(0xffffffffu, lo);
            if (mh == 0u) break;
            const u64 wkey = ((u64)mh << 32) | (u64)ml;
            const int a_   = (int)(0xFFFFFFFFu - ml);

            float4 w;
            if (lane == 0) w = __ldg(&gb[a_]);
            w.x = __shfl_sync(0xffffffffu, w.x, 0);
            w.y = __shfl_sync(0xffffffffu, w.y, 0);
            w.z = __shfl_sync(0xffffffffu, w.z, 0);
            w.w = __shfl_sync(0xffffffffu, w.w, 0);

            bool sup = false;
            for (int a = lane; a < acc; a += 32)
                if (iou_gt(w, abox[a])) sup = true;
            sup = (__ballot_sync(0xffffffffu, sup) != 0u);

            if (!sup) {
                if (lane == 0) {
                    abox[acc] = w;
                    float* o = out + ((size_t)b * TOPK + acc) * 6;
                    o[0] = __ldg(&gc[a_]);
                    o[1] = __uint_as_float(mh ^ 0x80000000u);
                    o[2] = w.x; o[3] = w.y; o[4] = w.z; o[5] = w.w;
                }
                acc++;
            }
            last = wkey;
            __syncwarp();
        }
    }
}

// ---------------------------------------------------------------------------
extern "C" void kernel_launch(void* const* d_in, const int* in_sizes, int n_in,
                              void* d_out, int out_size)
{
    const float* y   = (const float*)d_in[0];
    float*       out = (float*)d_out;

    const int dec_smem = 64 * NCH * 4;    // 23808 B
    cudaFuncSetAttribute(decode_kernel,
                         cudaFuncAttributeMaxDynamicSharedMemorySize, dec_smem);
    dim3 dgrid((NA + 63) / 64, NB);
    decode_kernel<<<dgrid, 256, dec_smem>>>(y);

    const int nms_smem = CANDN * 8 + CANDN * 16 + CANDN * 4 + TOPK * 16; // 31872
    cudaFuncSetAttribute(nms_kernel,
                         cudaFuncAttributeMaxDynamicSharedMemorySize, nms_smem);
    nms_kernel<<<NB, 1024, nms_smem>>>(out);
}